// round 14
// baseline (speedup 1.0000x reference)
#include <cuda_runtime.h>
#include <cuda_bf16.h>

typedef unsigned long long u64;
typedef unsigned int u32;

#define NB 4
#define NA 49104
#define NC 90
#define MAXDET 100
#define NPAIR (NB * NC)
#define NEGV (-1e30f)
#define SCORE_THR 0.01f
#define IOU_THR 0.1f

// Candidate prefix: scores > T0 (uniform data -> ~1964 per pair)
#define T0 0.96f
#define BINSCALE 51200.0f   // maps (T0, 1.0] onto [0, 2048)
#define NSH 8               // counter shards per pair
#define SCAP 512            // capacity per shard (mean ~245, +17 sigma margin)
#define CAP (NSH * SCAP)    // 4096
#define NBIN 2048

#define TG 256           // gather block
#define TF2 256          // fused block
#define T1 1024          // fallback block
#define IPT 48

// ---------------- global scratch ----------------
__device__ u64  g_cand[(size_t)NPAIR * CAP];
__device__ int  g_cnt[NPAIR * NSH];
__device__ int  g_flag[NPAIR];
__device__ float g_ks[NPAIR * MAXDET];
__device__ int   g_ka[NPAIR * MAXDET];
__device__ int   g_kc[NPAIR];

// ---------------------------------------------------------------------------
__global__ void init_kernel()
{
    int idx = blockIdx.x * blockDim.x + threadIdx.x;
    if (idx < NPAIR * NSH) g_cnt[idx] = 0;
    if (idx < NPAIR) g_flag[idx] = 0;
}

// ---------------------------------------------------------------------------
// Gather: fully coalesced float4 scan of classification; sharded counters.
// ---------------------------------------------------------------------------
__device__ __forceinline__ void push_cand(u32 flat, float s, int sh)
{
    const u32 per = (u32)NA * NC;
    int b = flat / per;
    u32 r = flat - (u32)b * per;
    int a = r / NC;
    int c = (int)(r - (u32)a * NC);
    int pair = b * NC + c;
    int pos = atomicAdd(&g_cnt[pair * NSH + sh], 1);
    if (pos < SCAP) {
        u64 key = ((u64)__float_as_uint(s) << 32) | (u32)(0xFFFFFFFFu - (u32)a);
        g_cand[(size_t)pair * CAP + sh * SCAP + pos] = key;
    }
}

__global__ __launch_bounds__(TG) void gather_kernel(const float* __restrict__ cls)
{
    const float4* __restrict__ p = (const float4*)cls;
    const u32 total = ((u32)NB * NA * NC) / 4;   // float4 elements (divisible)
    const u32 stride = gridDim.x * TG;
    const int sh = threadIdx.x & (NSH - 1);

    for (u32 idx = blockIdx.x * TG + threadIdx.x; idx < total; idx += stride) {
        float4 v = p[idx];
        float mx = fmaxf(fmaxf(v.x, v.y), fmaxf(v.z, v.w));
        if (mx > T0) {
            u32 flat = idx * 4u;
            if (v.x > T0) push_cand(flat + 0u, v.x, sh);
            if (v.y > T0) push_cand(flat + 1u, v.y, sh);
            if (v.z > T0) push_cand(flat + 2u, v.z, sh);
            if (v.w > T0) push_cand(flat + 3u, v.w, sh);
        }
    }
}

// ---------------------------------------------------------------------------
// Fused: counting-sort candidates (desc by (score, anchor asc)) + cooperative
// greedy NMS, 64 candidates per round (2 per lane), software-pipelined box
// loads. 8 warps share the kept-list scan, warp 0 does the serial fixup.
// One CTA per pair, 3 CTAs/SM.
// ---------------------------------------------------------------------------
#define DYN_BYTES (CAP * 8 + NBIN * 4 * 2)

__global__ __launch_bounds__(TF2, 3) void fused_kernel(const float* __restrict__ boxes)
{
    const int pair = blockIdx.x;
    const int b = pair / NC;
    const float4* __restrict__ bb = (const float4*)(boxes + (size_t)b * NA * 4);
    const int t = threadIdx.x;

    extern __shared__ char dyn[];
    u64* skey     = (u64*)dyn;                   // CAP * 8
    u32* binstart = (u32*)(dyn + CAP * 8);       // NBIN * 4
    u32* bincnt   = binstart + NBIN;             // NBIN * 4

    __shared__ float4 kb[MAXDET];
    __shared__ float  karea[MAXDET];
    __shared__ float  ksc[MAXDET];
    __shared__ int    kan[MAXDET];
    __shared__ u32    warpsum[8];
    __shared__ u32    sm_ok0[8];
    __shared__ u32    sm_ok1[8];
    __shared__ int    s_cnt_sh[NSH];
    __shared__ int    s_keptw, s_bad;

    if (t < NSH) {
        int c = g_cnt[pair * NSH + t];
        s_cnt_sh[t] = c;
        if (t == 0) s_bad = 0;
    }
    __syncthreads();
    if (t < NSH && s_cnt_sh[t] > SCAP) atomicExch(&s_bad, 1);
    for (int i = t; i < NBIN; i += TF2) bincnt[i] = 0;
    __syncthreads();
    if (s_bad) { if (t == 0) g_flag[pair] = 1; return; }

    const u64* __restrict__ cand = &g_cand[(size_t)pair * CAP];

    // histogram (bin index flipped for descending order)
#pragma unroll
    for (int sh = 0; sh < NSH; sh++) {
        int cs = s_cnt_sh[sh];
        for (int i = t; i < cs; i += TF2) {
            u64 k = cand[sh * SCAP + i];
            float s = __uint_as_float((u32)(k >> 32));
            int bin = (int)((s - T0) * BINSCALE);
            bin = min(max(bin, 0), NBIN - 1);
            atomicAdd(&bincnt[NBIN - 1 - bin], 1u);
        }
    }
    __syncthreads();

    // exclusive scan over NBIN bins (8 bins/thread, 8 warps)
    {
        u32 c[8];
        u32 tsum = 0;
#pragma unroll
        for (int q = 0; q < 8; q++) { c[q] = bincnt[8 * t + q]; tsum += c[q]; }
        u32 lane = t & 31, w = t >> 5;
        u32 x = tsum;
#pragma unroll
        for (int o = 1; o < 32; o <<= 1) {
            u32 y = __shfl_up_sync(0xffffffffu, x, o);
            if (lane >= (u32)o) x += y;
        }
        if (lane == 31) warpsum[w] = x;
        __syncthreads();
        if (t == 0) {
            u32 r = 0;
#pragma unroll
            for (int i2 = 0; i2 < 8; i2++) { u32 v = warpsum[i2]; warpsum[i2] = r; r += v; }
        }
        __syncthreads();
        u32 ex = warpsum[w] + x - tsum;
#pragma unroll
        for (int q = 0; q < 8; q++) { binstart[8 * t + q] = ex; ex += c[q]; }
    }
    __syncthreads();

    // scatter (binstart becomes end cursor)
    int cnt = 0;
#pragma unroll
    for (int sh = 0; sh < NSH; sh++) cnt += s_cnt_sh[sh];
#pragma unroll
    for (int sh = 0; sh < NSH; sh++) {
        int cs = s_cnt_sh[sh];
        for (int i = t; i < cs; i += TF2) {
            u64 k = cand[sh * SCAP + i];
            float s = __uint_as_float((u32)(k >> 32));
            int bin = (int)((s - T0) * BINSCALE);
            bin = min(max(bin, 0), NBIN - 1);
            u32 pos = atomicAdd(&binstart[NBIN - 1 - bin], 1u);
            skey[pos] = k;
        }
    }
    __syncthreads();

    // fix within-bin order (descending u64 => score desc, anchor asc)
    for (int bin = t; bin < NBIN; bin += TF2) {
        int c2 = (int)bincnt[bin];
        if (c2 >= 2) {
            int st = (int)binstart[bin] - c2;
            for (int x = st + 1; x < st + c2; x++) {
                u64 kk = skey[x];
                int y = x - 1;
                while (y >= st && skey[y] < kk) { skey[y + 1] = skey[y]; y--; }
                skey[y + 1] = kk;
            }
        }
    }
    if (t == 0) s_keptw = 0;
    __syncthreads();

    // ---- cooperative greedy, 64 candidates/round (2 per lane), prefetch ----
    {
        const int lane = t & 31;
        const int wrp  = t >> 5;
        int i = 0;
        // preload round 0: cand0 = i+lane, cand1 = i+32+lane
        bool act0 = lane < cnt;
        bool act1 = (32 + lane) < cnt;
        u64 k0 = act0 ? skey[lane] : 0ull;
        u64 k1 = act1 ? skey[32 + lane] : 0ull;
        u32 anc0 = 0xFFFFFFFFu - (u32)k0;
        u32 anc1 = 0xFFFFFFFFu - (u32)k1;
        float4 bx0 = act0 ? bb[anc0] : make_float4(0.f, 0.f, 0.f, 0.f);
        float4 bx1 = act1 ? bb[anc1] : make_float4(0.f, 0.f, 0.f, 0.f);

        for (;;) {
            int kept = s_keptw;                 // valid: barrier at loop tail
            if (kept >= MAXDET || i >= cnt) break;

            // prefetch round i+64 (hides L2 latency behind the kept-scan)
            int pidx0 = i + 64 + lane;
            int pidx1 = i + 96 + lane;
            bool pact0 = pidx0 < cnt;
            bool pact1 = pidx1 < cnt;
            u64 pk0 = pact0 ? skey[pidx0] : 0ull;
            u64 pk1 = pact1 ? skey[pidx1] : 0ull;
            u32 panc0 = 0xFFFFFFFFu - (u32)pk0;
            u32 panc1 = 0xFFFFFFFFu - (u32)pk1;
            float4 pbx0 = pact0 ? bb[panc0] : make_float4(0.f, 0.f, 0.f, 0.f);
            float4 pbx1 = pact1 ? bb[panc1] : make_float4(0.f, 0.f, 0.f, 0.f);

            float barea0 = (bx0.z - bx0.x) * (bx0.w - bx0.y);
            float barea1 = (bx1.z - bx1.x) * (bx1.w - bx1.y);

            // stride-8 slice of the kept list per warp; kb/karea loaded once
            bool ok0 = act0, ok1 = act1;
            for (int j = wrp; j < kept; j += 8) {
                float4 s4 = kb[j];
                float ka_ = karea[j];
                {
                    float iy1 = fmaxf(s4.x, bx0.x);
                    float ix1 = fmaxf(s4.y, bx0.y);
                    float iy2 = fminf(s4.z, bx0.z);
                    float ix2 = fminf(s4.w, bx0.w);
                    float inter = fmaxf(iy2 - iy1, 0.0f) * fmaxf(ix2 - ix1, 0.0f);
                    float iou = inter / (ka_ + barea0 - inter + 1e-8f);
                    if (iou > IOU_THR) ok0 = false;
                }
                {
                    float iy1 = fmaxf(s4.x, bx1.x);
                    float ix1 = fmaxf(s4.y, bx1.y);
                    float iy2 = fminf(s4.z, bx1.z);
                    float ix2 = fminf(s4.w, bx1.w);
                    float inter = fmaxf(iy2 - iy1, 0.0f) * fmaxf(ix2 - ix1, 0.0f);
                    float iou = inter / (ka_ + barea1 - inter + 1e-8f);
                    if (iou > IOU_THR) ok1 = false;
                }
            }
            u32 wm0 = __ballot_sync(0xffffffffu, ok0);
            u32 wm1 = __ballot_sync(0xffffffffu, ok1);
            if (lane == 0) { sm_ok0[wrp] = wm0; sm_ok1[wrp] = wm1; }
            __syncthreads();

            if (wrp == 0) {
                float sc0 = __uint_as_float((u32)(k0 >> 32));
                float sc1 = __uint_as_float((u32)(k1 >> 32));
                u32 prov0 = sm_ok0[0] & sm_ok0[1] & sm_ok0[2] & sm_ok0[3] &
                            sm_ok0[4] & sm_ok0[5] & sm_ok0[6] & sm_ok0[7];
                u32 prov1 = sm_ok1[0] & sm_ok1[1] & sm_ok1[2] & sm_ok1[3] &
                            sm_ok1[4] & sm_ok1[5] & sm_ok1[6] & sm_ok1[7];

                // ---- phase A: fixup first 32 (they precede the second 32) ----
                u32 m = prov0;
                while (m && kept < MAXDET) {
                    int l = __ffs(m) - 1;
                    m &= m - 1;
                    float ay1 = __shfl_sync(0xffffffffu, bx0.x, l);
                    float ax1 = __shfl_sync(0xffffffffu, bx0.y, l);
                    float ay2 = __shfl_sync(0xffffffffu, bx0.z, l);
                    float ax2 = __shfl_sync(0xffffffffu, bx0.w, l);
                    float asc = __shfl_sync(0xffffffffu, sc0, l);
                    u32   aan = __shfl_sync(0xffffffffu, anc0, l);
                    float aarea = (ay2 - ay1) * (ax2 - ax1);
                    if (lane == 0) {
                        kb[kept] = make_float4(ay1, ax1, ay2, ax2);
                        karea[kept] = aarea;
                        ksc[kept] = asc;
                        kan[kept] = (int)aan;
                    }
                    __syncwarp();
                    kept++;
                    if (kept >= MAXDET) break;
                    // retest later batch0 provisionals AND all batch1 provisionals
                    bool fail0 = false, fail1 = false;
                    if (((prov0 >> lane) & 1u) && lane > l) {
                        float iy1 = fmaxf(ay1, bx0.x);
                        float ix1 = fmaxf(ax1, bx0.y);
                        float iy2 = fminf(ay2, bx0.z);
                        float ix2 = fminf(ax2, bx0.w);
                        float inter = fmaxf(iy2 - iy1, 0.0f) * fmaxf(ix2 - ix1, 0.0f);
                        float iou = inter / (aarea + barea0 - inter + 1e-8f);
                        if (iou > IOU_THR) fail0 = true;
                    }
                    if ((prov1 >> lane) & 1u) {
                        float iy1 = fmaxf(ay1, bx1.x);
                        float ix1 = fmaxf(ax1, bx1.y);
                        float iy2 = fminf(ay2, bx1.z);
                        float ix2 = fminf(ax2, bx1.w);
                        float inter = fmaxf(iy2 - iy1, 0.0f) * fmaxf(ix2 - ix1, 0.0f);
                        float iou = inter / (aarea + barea1 - inter + 1e-8f);
                        if (iou > IOU_THR) fail1 = true;
                    }
                    u32 fm0 = __ballot_sync(0xffffffffu, fail0);
                    u32 fm1 = __ballot_sync(0xffffffffu, fail1);
                    prov0 &= ~fm0;
                    m &= ~fm0;
                    prov1 &= ~fm1;
                }
                // ---- phase B: fixup second 32 ----
                m = prov1;
                while (m && kept < MAXDET) {
                    int l = __ffs(m) - 1;
                    m &= m - 1;
                    float ay1 = __shfl_sync(0xffffffffu, bx1.x, l);
                    float ax1 = __shfl_sync(0xffffffffu, bx1.y, l);
                    float ay2 = __shfl_sync(0xffffffffu, bx1.z, l);
                    float ax2 = __shfl_sync(0xffffffffu, bx1.w, l);
                    float asc = __shfl_sync(0xffffffffu, sc1, l);
                    u32   aan = __shfl_sync(0xffffffffu, anc1, l);
                    float aarea = (ay2 - ay1) * (ax2 - ax1);
                    if (lane == 0) {
                        kb[kept] = make_float4(ay1, ax1, ay2, ax2);
                        karea[kept] = aarea;
                        ksc[kept] = asc;
                        kan[kept] = (int)aan;
                    }
                    __syncwarp();
                    kept++;
                    if (kept >= MAXDET) break;
                    bool fail1b = false;
                    if (((prov1 >> lane) & 1u) && lane > l) {
                        float iy1 = fmaxf(ay1, bx1.x);
                        float ix1 = fmaxf(ax1, bx1.y);
                        float iy2 = fminf(ay2, bx1.z);
                        float ix2 = fminf(ax2, bx1.w);
                        float inter = fmaxf(iy2 - iy1, 0.0f) * fmaxf(ix2 - ix1, 0.0f);
                        float iou = inter / (aarea + barea1 - inter + 1e-8f);
                        if (iou > IOU_THR) fail1b = true;
                    }
                    u32 fm = __ballot_sync(0xffffffffu, fail1b);
                    prov1 &= ~fm;
                    m &= ~fm;
                }
                if (lane == 0) s_keptw = kept;
            }
            i += 64;
            __syncthreads();   // publish s_keptw + kb updates before next scan
            k0 = pk0; anc0 = panc0; bx0 = pbx0; act0 = pact0;
            k1 = pk1; anc1 = panc1; bx1 = pbx1; act1 = pact1;
        }
    }
    __syncthreads();

    int kept = s_keptw;
    if (kept < MAXDET) { if (t == 0) g_flag[pair] = 1; return; }

    if (t < kept) {
        g_ks[pair * MAXDET + t] = ksc[t];
        g_ka[pair * MAXDET + t] = kan[t];
    }
    if (t == 0) g_kc[pair] = kept;
}

// ---------------------------------------------------------------------------
// Fallback: full per-pair NMS, persistent grid-stride over flagged pairs
// (expected: none flagged).
// ---------------------------------------------------------------------------
__global__ __launch_bounds__(T1) void fallback_kernel(const float* __restrict__ boxes,
                                                      const float* __restrict__ cls)
{
    const int t = threadIdx.x;

    __shared__ float wv[32];
    __shared__ int   wi[32];
    __shared__ float sbox[4];
    __shared__ int   ssel;
    __shared__ float ks_s[MAXDET];
    __shared__ int   ka_s[MAXDET];
    __shared__ int   scnt;

    for (int pair = blockIdx.x; pair < NPAIR; pair += gridDim.x) {
        __syncthreads();                 // separate iterations
        if (!g_flag[pair]) continue;     // uniform per block

        const int b = pair / NC;
        const int c = pair % NC;
        const float4* __restrict__ bb = (const float4*)(boxes + (size_t)b * NA * 4);
        const float* __restrict__ sc = cls + (size_t)b * NA * NC + c;

        float s[IPT];
#pragma unroll
        for (int i = 0; i < IPT; i++) {
            int a = i * T1 + t;
            float v = (a < NA) ? sc[(size_t)a * NC] : NEGV;
            s[i] = (v > SCORE_THR) ? v : NEGV;
        }

        if (t == 0) scnt = 0;

        bool exhausted = false;

        for (int it = 0; it < MAXDET; it++) {
            float bv = NEGV;
            int   bi = 0x7FFFFFFF;
#pragma unroll
            for (int i = 0; i < IPT; i++) {
                if (s[i] > bv) { bv = s[i]; bi = i * T1 + t; }
            }
#pragma unroll
            for (int o = 16; o; o >>= 1) {
                float ov = __shfl_down_sync(0xffffffffu, bv, o);
                int   oi = __shfl_down_sync(0xffffffffu, bi, o);
                if (ov > bv || (ov == bv && oi < bi)) { bv = ov; bi = oi; }
            }
            if ((t & 31) == 0) { wv[t >> 5] = bv; wi[t >> 5] = bi; }
            __syncthreads();
            if (t < 32) {
                bv = wv[t]; bi = wi[t];
#pragma unroll
                for (int o = 16; o; o >>= 1) {
                    float ov = __shfl_down_sync(0xffffffffu, bv, o);
                    int   oi = __shfl_down_sync(0xffffffffu, bi, o);
                    if (ov > bv || (ov == bv && oi < bi)) { bv = ov; bi = oi; }
                }
                if (t == 0) {
                    if (bv > -0.5e30f) {
                        float4 bx = bb[bi];
                        sbox[0] = bx.x; sbox[1] = bx.y; sbox[2] = bx.z; sbox[3] = bx.w;
                        ssel = bi;
                        int k = scnt;
                        ks_s[k] = bv;
                        ka_s[k] = bi;
                        scnt = k + 1;
                    } else {
                        ssel = -1;
                    }
                }
            }
            __syncthreads();

            int sel = ssel;
            if (sel < 0) { exhausted = true; break; }

            float y1 = sbox[0], x1 = sbox[1], y2 = sbox[2], x2 = sbox[3];
            float sarea = (y2 - y1) * (x2 - x1);
#pragma unroll
            for (int i = 0; i < IPT; i++) {
                if (s[i] > -1e29f) {
                    int a = i * T1 + t;
                    float4 bx = bb[a];
                    float iy1 = fmaxf(y1, bx.x);
                    float ix1 = fmaxf(x1, bx.y);
                    float iy2 = fminf(y2, bx.z);
                    float ix2 = fminf(x2, bx.w);
                    float inter = fmaxf(iy2 - iy1, 0.0f) * fmaxf(ix2 - ix1, 0.0f);
                    float barea = (bx.z - bx.x) * (bx.w - bx.y);
                    float iou = inter / (sarea + barea - inter + 1e-8f);
                    if (iou > IOU_THR) s[i] = NEGV;
                    if (a == sel)      s[i] = NEGV;
                }
            }
            __syncthreads();
        }

        __syncthreads();
        if (t == 0) {
            int cnt = scnt;
            if (exhausted) {
                for (int k = 0; k < cnt; k++) {
                    if (ka_s[k] == 0) {
                        for (int m2 = k; m2 < cnt - 1; m2++) {
                            ks_s[m2] = ks_s[m2 + 1];
                            ka_s[m2] = ka_s[m2 + 1];
                        }
                        cnt--;
                        break;
                    }
                }
                scnt = cnt;
            }
        }
        __syncthreads();
        int cnt = scnt;
        int base2 = pair * MAXDET;
        if (t < cnt) {
            g_ks[base2 + t] = ks_s[t];
            g_ka[base2 + t] = ka_s[t];
        }
        if (t == 0) g_kc[pair] = cnt;
    }
}

// ---------------------------------------------------------------------------
// topk: histogram-select over all kept keys, exact rank selection of the
// top-100 compacted prefix. Serial 90-way merge retained as a guarded
// fallback for pathological distributions.
// ---------------------------------------------------------------------------
#define TT 512
#define CAPC 1024
#define TOPK_DYN (NC * MAXDET * 8)

__device__ __forceinline__ int desc_bin(u64 k)
{
    float s = __uint_as_float((u32)(k >> 32));
    int bin = (int)((s - T0) * BINSCALE);
    bin = min(max(bin, 0), NBIN - 1);
    return NBIN - 1 - bin;
}

__global__ __launch_bounds__(TT) void topk_kernel(const float* __restrict__ boxes,
                                                  float* __restrict__ out)
{
    const int b = blockIdx.x;
    const int t = threadIdx.x;

    extern __shared__ u64 skey[];   // NC*MAXDET

    __shared__ int   cnts[NC];
    __shared__ u32   hist[NBIN];    // histogram -> inclusive cumulative
    __shared__ u64   comp[CAPC];
    __shared__ u64   sel[MAXDET];
    __shared__ u32   warpsum[16];
    __shared__ int   s_cut, s_M, s_nw;

    if (t < NC) cnts[t] = g_kc[b * NC + t];
    for (int i = t; i < NBIN; i += TT) hist[i] = 0;
    if (t == 0) { s_cut = NBIN - 1; s_M = 0; }
    __syncthreads();

    for (int i = t; i < NC * MAXDET; i += TT) {
        int c = i / MAXDET, j = i % MAXDET;
        u64 key = 0ull;
        if (j < cnts[c]) {
            int pb = (b * NC + c) * MAXDET + j;
            float sv = g_ks[pb];
            int   av = g_ka[pb];
            u32 flat = (u32)av * NC + (u32)c;
            key = ((u64)__float_as_uint(sv) << 32) | (0xFFFFFFFFu - flat);
            atomicAdd(&hist[desc_bin(key)], 1u);
        }
        skey[i] = key;
    }
    __syncthreads();

    // inclusive prefix over NBIN bins (4 bins/thread, 16 warps)
    {
        u32 c0 = hist[4 * t], c1 = hist[4 * t + 1];
        u32 c2 = hist[4 * t + 2], c3 = hist[4 * t + 3];
        u32 tsum = c0 + c1 + c2 + c3;
        u32 lane = t & 31, w = t >> 5;
        u32 x = tsum;
#pragma unroll
        for (int o = 1; o < 32; o <<= 1) {
            u32 y = __shfl_up_sync(0xffffffffu, x, o);
            if (lane >= (u32)o) x += y;
        }
        if (lane == 31) warpsum[w] = x;
        __syncthreads();
        if (t == 0) {
            u32 r = 0;
#pragma unroll
            for (int i2 = 0; i2 < 16; i2++) { u32 v = warpsum[i2]; warpsum[i2] = r; r += v; }
        }
        __syncthreads();
        u32 ex = warpsum[w] + x - tsum;   // exclusive prefix of this thread's 4 bins
        hist[4 * t + 0] = ex + c0;
        hist[4 * t + 1] = ex + c0 + c1;
        hist[4 * t + 2] = ex + c0 + c1 + c2;
        hist[4 * t + 3] = ex + tsum;
    }
    __syncthreads();

    // find cutoff: first bin d (desc order) with cumulative >= MAXDET
    for (int q = 0; q < 4; q++) {
        int d = 4 * t + q;
        u32 cum = hist[d];
        u32 prev = (d == 0) ? 0u : hist[d - 1];
        if (cum >= (u32)MAXDET && prev < (u32)MAXDET) s_cut = d;  // unique writer
    }
    __syncthreads();
    int cut = s_cut;

    // compact keys in bins <= cut
    for (int i = t; i < NC * MAXDET; i += TT) {
        u64 k = skey[i];
        if (k && desc_bin(k) <= cut) {
            int p = atomicAdd(&s_M, 1);
            if (p < CAPC) comp[p] = k;
        }
    }
    __syncthreads();
    int M = s_M;

    if (M <= CAPC) {
        // exact rank selection: rank = #{keys greater}; keys are unique
        for (int x = t; x < M; x += TT) {
            u64 mk = comp[x];
            int rank = 0;
            for (int j = 0; j < M; j++) rank += (comp[j] > mk);
            if (rank < MAXDET) sel[rank] = mk;
        }
        if (t == 0) s_nw = (M < MAXDET) ? M : MAXDET;
    } else if (t < 32) {
        // fallback: serial 90-way merge of sorted per-class lists
        const int lane = t;
        u64 hk[3];
        int hj[3];
#pragma unroll
        for (int q = 0; q < 3; q++) {
            int c = lane + q * 32;
            hj[q] = 0;
            hk[q] = (c < NC) ? skey[c * MAXDET] : 0ull;
        }
        int nw = MAXDET;
        for (int k = 0; k < MAXDET; k++) {
            u64 bvk = hk[0];
            int bq = 0;
            if (hk[1] > bvk) { bvk = hk[1]; bq = 1; }
            if (hk[2] > bvk) { bvk = hk[2]; bq = 2; }
            u64 rv = bvk;
            int rl = lane, rq = bq;
#pragma unroll
            for (int o = 16; o; o >>= 1) {
                u64 ov = __shfl_down_sync(0xffffffffu, rv, o);
                int ol = __shfl_down_sync(0xffffffffu, rl, o);
                int oq = __shfl_down_sync(0xffffffffu, rq, o);
                if (ov > rv) { rv = ov; rl = ol; rq = oq; }
            }
            rv = __shfl_sync(0xffffffffu, rv, 0);
            rl = __shfl_sync(0xffffffffu, rl, 0);
            rq = __shfl_sync(0xffffffffu, rq, 0);
            if (rv == 0ull) { nw = k; break; }
            if (lane == 0) sel[k] = rv;
            if (lane == rl) {
                hj[rq]++;
                int c = lane + rq * 32;
                hk[rq] = (hj[rq] < MAXDET) ? skey[c * MAXDET + hj[rq]] : 0ull;
            }
        }
        if (lane == 0) s_nw = nw;
    }
    __syncthreads();

    int nw = s_nw;
    const float4* __restrict__ bb = (const float4*)(boxes + (size_t)b * NA * 4);
    float* ob = out + (size_t)b * MAXDET * 4;
    float* os = out + (size_t)NB * MAXDET * 4 + (size_t)b * MAXDET;
    float* ol = out + (size_t)NB * MAXDET * 5 + (size_t)b * MAXDET;

    if (t < MAXDET) {
        if (t < nw) {
            u64 rv = sel[t];
            u32 flat = 0xFFFFFFFFu - (u32)rv;
            int anchor = (int)(flat / NC);
            int lab = (int)(flat % NC);
            float4 bx = bb[anchor];
            ob[t * 4 + 0] = bx.x;
            ob[t * 4 + 1] = bx.y;
            ob[t * 4 + 2] = bx.z;
            ob[t * 4 + 3] = bx.w;
            os[t] = __uint_as_float((u32)(rv >> 32));
            ol[t] = (float)lab;
        } else {
            ob[t * 4 + 0] = -1.0f;
            ob[t * 4 + 1] = -1.0f;
            ob[t * 4 + 2] = -1.0f;
            ob[t * 4 + 3] = -1.0f;
            os[t] = -1.0f;
            ol[t] = -1.0f;
        }
    }
}

// ---------------------------------------------------------------------------
extern "C" void kernel_launch(void* const* d_in, const int* in_sizes, int n_in,
                              void* d_out, int out_size)
{
    const float* boxes = (const float*)d_in[0];
    const float* cls   = (const float*)d_in[1];
    float* out = (float*)d_out;

    cudaFuncSetAttribute(fused_kernel, cudaFuncAttributeMaxDynamicSharedMemorySize, DYN_BYTES);
    cudaFuncSetAttribute(topk_kernel, cudaFuncAttributeMaxDynamicSharedMemorySize, TOPK_DYN);

    init_kernel<<<8, 512>>>();
    gather_kernel<<<2160, TG>>>(cls);
    fused_kernel<<<NPAIR, TF2, DYN_BYTES>>>(boxes);
    fallback_kernel<<<148, T1>>>(boxes, cls);
    topk_kernel<<<NB, TT, TOPK_DYN>>>(boxes, out);
}

// round 15
// speedup vs baseline: 1.1288x; 1.1288x over previous
#include <cuda_runtime.h>
#include <cuda_bf16.h>

typedef unsigned long long u64;
typedef unsigned int u32;

#define NB 4
#define NA 49104
#define NC 90
#define MAXDET 100
#define NPAIR (NB * NC)
#define NEGV (-1e30f)
#define SCORE_THR 0.01f
#define IOU_THR 0.1f

// Candidate prefix: scores > T0 (uniform data -> ~1964 per pair)
#define T0 0.96f
#define BINSCALE 51200.0f   // maps (T0, 1.0] onto [0, 2048)
#define NSH 16              // counter shards per pair
#define SCAP 256            // capacity per shard (mean ~123, +12 sigma margin)
#define CAP (NSH * SCAP)    // 4096
#define NBIN 2048

#define TG 256           // gather block
#define TF2 256          // fused block
#define T1 1024          // fallback block
#define IPT 48

// ---------------- global scratch ----------------
__device__ u64  g_cand[(size_t)NPAIR * CAP];
__device__ int  g_cnt[NPAIR * NSH];
__device__ int  g_flag[NPAIR];
__device__ float g_ks[NPAIR * MAXDET];
__device__ int   g_ka[NPAIR * MAXDET];
__device__ int   g_kc[NPAIR];

// ---------------------------------------------------------------------------
__global__ void init_kernel()
{
    int idx = blockIdx.x * blockDim.x + threadIdx.x;
    if (idx < NPAIR * NSH) g_cnt[idx] = 0;
    if (idx < NPAIR) g_flag[idx] = 0;
}

// ---------------------------------------------------------------------------
// Gather: fully coalesced float4 scan of classification; sharded counters.
// ---------------------------------------------------------------------------
__device__ __forceinline__ void push_cand(u32 flat, float s, int sh)
{
    const u32 per = (u32)NA * NC;
    int b = flat / per;
    u32 r = flat - (u32)b * per;
    int a = r / NC;
    int c = (int)(r - (u32)a * NC);
    int pair = b * NC + c;
    int pos = atomicAdd(&g_cnt[pair * NSH + sh], 1);
    if (pos < SCAP) {
        u64 key = ((u64)__float_as_uint(s) << 32) | (u32)(0xFFFFFFFFu - (u32)a);
        g_cand[(size_t)pair * CAP + sh * SCAP + pos] = key;
    }
}

__global__ __launch_bounds__(TG) void gather_kernel(const float* __restrict__ cls)
{
    const float4* __restrict__ p = (const float4*)cls;
    const u32 total = ((u32)NB * NA * NC) / 4;   // float4 elements (divisible)
    const u32 stride = gridDim.x * TG;
    const int sh = threadIdx.x & (NSH - 1);

    for (u32 idx = blockIdx.x * TG + threadIdx.x; idx < total; idx += stride) {
        float4 v = p[idx];
        float mx = fmaxf(fmaxf(v.x, v.y), fmaxf(v.z, v.w));
        if (mx > T0) {
            u32 flat = idx * 4u;
            if (v.x > T0) push_cand(flat + 0u, v.x, sh);
            if (v.y > T0) push_cand(flat + 1u, v.y, sh);
            if (v.z > T0) push_cand(flat + 2u, v.z, sh);
            if (v.w > T0) push_cand(flat + 3u, v.w, sh);
        }
    }
}

// ---------------------------------------------------------------------------
// Fused: counting-sort candidates (desc by (score, anchor asc)) + cooperative
// greedy NMS with software-pipelined box loads (32 candidates/round). 8 warps
// share the kept-list scan, warp 0 does the serial fixup. 3 CTAs/SM.
// ---------------------------------------------------------------------------
#define DYN_BYTES (CAP * 8 + NBIN * 4 * 2)

__global__ __launch_bounds__(TF2, 3) void fused_kernel(const float* __restrict__ boxes)
{
    const int pair = blockIdx.x;
    const int b = pair / NC;
    const float4* __restrict__ bb = (const float4*)(boxes + (size_t)b * NA * 4);
    const int t = threadIdx.x;

    extern __shared__ char dyn[];
    u64* skey     = (u64*)dyn;                   // CAP * 8
    u32* binstart = (u32*)(dyn + CAP * 8);       // NBIN * 4
    u32* bincnt   = binstart + NBIN;             // NBIN * 4

    __shared__ float4 kb[MAXDET];
    __shared__ float  karea[MAXDET];
    __shared__ float  ksc[MAXDET];
    __shared__ int    kan[MAXDET];
    __shared__ u32    warpsum[8];
    __shared__ u32    sm_ok[8];
    __shared__ int    s_cnt_sh[NSH];
    __shared__ int    s_keptw, s_bad;

    if (t < NSH) {
        int c = g_cnt[pair * NSH + t];
        s_cnt_sh[t] = c;
        if (t == 0) s_bad = 0;
    }
    __syncthreads();
    if (t < NSH && s_cnt_sh[t] > SCAP) atomicExch(&s_bad, 1);
    for (int i = t; i < NBIN; i += TF2) bincnt[i] = 0;
    __syncthreads();
    if (s_bad) { if (t == 0) g_flag[pair] = 1; return; }

    const u64* __restrict__ cand = &g_cand[(size_t)pair * CAP];

    // histogram (bin index flipped for descending order)
#pragma unroll
    for (int sh = 0; sh < NSH; sh++) {
        int cs = s_cnt_sh[sh];
        for (int i = t; i < cs; i += TF2) {
            u64 k = cand[sh * SCAP + i];
            float s = __uint_as_float((u32)(k >> 32));
            int bin = (int)((s - T0) * BINSCALE);
            bin = min(max(bin, 0), NBIN - 1);
            atomicAdd(&bincnt[NBIN - 1 - bin], 1u);
        }
    }
    __syncthreads();

    // exclusive scan over NBIN bins (8 bins/thread, 8 warps)
    {
        u32 c[8];
        u32 tsum = 0;
#pragma unroll
        for (int q = 0; q < 8; q++) { c[q] = bincnt[8 * t + q]; tsum += c[q]; }
        u32 lane = t & 31, w = t >> 5;
        u32 x = tsum;
#pragma unroll
        for (int o = 1; o < 32; o <<= 1) {
            u32 y = __shfl_up_sync(0xffffffffu, x, o);
            if (lane >= (u32)o) x += y;
        }
        if (lane == 31) warpsum[w] = x;
        __syncthreads();
        if (t == 0) {
            u32 r = 0;
#pragma unroll
            for (int i2 = 0; i2 < 8; i2++) { u32 v = warpsum[i2]; warpsum[i2] = r; r += v; }
        }
        __syncthreads();
        u32 ex = warpsum[w] + x - tsum;
#pragma unroll
        for (int q = 0; q < 8; q++) { binstart[8 * t + q] = ex; ex += c[q]; }
    }
    __syncthreads();

    // scatter (binstart becomes end cursor)
    int cnt = 0;
#pragma unroll
    for (int sh = 0; sh < NSH; sh++) cnt += s_cnt_sh[sh];
#pragma unroll
    for (int sh = 0; sh < NSH; sh++) {
        int cs = s_cnt_sh[sh];
        for (int i = t; i < cs; i += TF2) {
            u64 k = cand[sh * SCAP + i];
            float s = __uint_as_float((u32)(k >> 32));
            int bin = (int)((s - T0) * BINSCALE);
            bin = min(max(bin, 0), NBIN - 1);
            u32 pos = atomicAdd(&binstart[NBIN - 1 - bin], 1u);
            skey[pos] = k;
        }
    }
    __syncthreads();

    // fix within-bin order (descending u64 => score desc, anchor asc)
    for (int bin = t; bin < NBIN; bin += TF2) {
        int c2 = (int)bincnt[bin];
        if (c2 >= 2) {
            int st = (int)binstart[bin] - c2;
            for (int x = st + 1; x < st + c2; x++) {
                u64 kk = skey[x];
                int y = x - 1;
                while (y >= st && skey[y] < kk) { skey[y + 1] = skey[y]; y--; }
                skey[y + 1] = kk;
            }
        }
    }
    if (t == 0) s_keptw = 0;
    __syncthreads();

    // ---- cooperative greedy with prefetch: candidate = t&31, slice = t>>5 ----
    {
        const int lane = t & 31;
        const int wrp  = t >> 5;
        int i = 0;
        // preload batch 0
        bool act = lane < cnt;
        u64 k = act ? skey[lane] : 0ull;
        u32 anc = 0xFFFFFFFFu - (u32)k;
        float4 bx = act ? bb[anc] : make_float4(0.f, 0.f, 0.f, 0.f);

        for (;;) {
            int kept = s_keptw;                 // valid: barrier at loop tail
            if (kept >= MAXDET || i >= cnt) break;

            // prefetch batch i+32 (hides L2 latency behind the kept-scan)
            int nidx = i + 32 + lane;
            bool nact = nidx < cnt;
            u64 nk = nact ? skey[nidx] : 0ull;
            u32 nanc = 0xFFFFFFFFu - (u32)nk;
            float4 nbx = nact ? bb[nanc] : make_float4(0.f, 0.f, 0.f, 0.f);

            float barea = (bx.z - bx.x) * (bx.w - bx.y);

            // stride-8 slice of the kept list per warp (<=13 IOU evals)
            bool ok = act;
            for (int j = wrp; j < kept; j += 8) {
                float4 s4 = kb[j];
                float iy1 = fmaxf(s4.x, bx.x);
                float ix1 = fmaxf(s4.y, bx.y);
                float iy2 = fminf(s4.z, bx.z);
                float ix2 = fminf(s4.w, bx.w);
                float inter = fmaxf(iy2 - iy1, 0.0f) * fmaxf(ix2 - ix1, 0.0f);
                float iou = inter / (karea[j] + barea - inter + 1e-8f);
                if (iou > IOU_THR) ok = false;
            }
            u32 wm = __ballot_sync(0xffffffffu, ok);
            if (lane == 0) sm_ok[wrp] = wm;
            __syncthreads();

            if (wrp == 0) {
                float sc_ = __uint_as_float((u32)(k >> 32));
                u32 prov = sm_ok[0] & sm_ok[1] & sm_ok[2] & sm_ok[3] &
                           sm_ok[4] & sm_ok[5] & sm_ok[6] & sm_ok[7];
                u32 m = prov;
                while (m && kept < MAXDET) {
                    int l = __ffs(m) - 1;
                    m &= m - 1;
                    float ay1 = __shfl_sync(0xffffffffu, bx.x, l);
                    float ax1 = __shfl_sync(0xffffffffu, bx.y, l);
                    float ay2 = __shfl_sync(0xffffffffu, bx.z, l);
                    float ax2 = __shfl_sync(0xffffffffu, bx.w, l);
                    float asc = __shfl_sync(0xffffffffu, sc_, l);
                    u32   aan = __shfl_sync(0xffffffffu, anc, l);
                    float aarea = (ay2 - ay1) * (ax2 - ax1);
                    if (lane == 0) {
                        kb[kept] = make_float4(ay1, ax1, ay2, ax2);
                        karea[kept] = aarea;
                        ksc[kept] = asc;
                        kan[kept] = (int)aan;
                    }
                    __syncwarp();
                    kept++;
                    if (kept >= MAXDET) break;
                    // re-test later provisional candidates vs this accept
                    bool fail = false;
                    if (((prov >> lane) & 1u) && lane > l) {
                        float iy1 = fmaxf(ay1, bx.x);
                        float ix1 = fmaxf(ax1, bx.y);
                        float iy2 = fminf(ay2, bx.z);
                        float ix2 = fminf(ax2, bx.w);
                        float inter = fmaxf(iy2 - iy1, 0.0f) * fmaxf(ix2 - ix1, 0.0f);
                        float iou = inter / (aarea + barea - inter + 1e-8f);
                        if (iou > IOU_THR) fail = true;
                    }
                    u32 fm = __ballot_sync(0xffffffffu, fail);
                    prov &= ~fm;
                    m &= ~fm;
                }
                if (lane == 0) s_keptw = kept;
            }
            i += 32;
            __syncthreads();   // publish s_keptw + kb updates before next scan
            k = nk; anc = nanc; bx = nbx; act = nact;
        }
    }
    __syncthreads();

    int kept = s_keptw;
    if (kept < MAXDET) { if (t == 0) g_flag[pair] = 1; return; }

    if (t < kept) {
        g_ks[pair * MAXDET + t] = ksc[t];
        g_ka[pair * MAXDET + t] = kan[t];
    }
    if (t == 0) g_kc[pair] = kept;
}

// ---------------------------------------------------------------------------
// Fallback: full per-pair NMS, persistent grid-stride over flagged pairs
// (expected: none flagged).
// ---------------------------------------------------------------------------
__global__ __launch_bounds__(T1) void fallback_kernel(const float* __restrict__ boxes,
                                                      const float* __restrict__ cls)
{
    const int t = threadIdx.x;

    __shared__ float wv[32];
    __shared__ int   wi[32];
    __shared__ float sbox[4];
    __shared__ int   ssel;
    __shared__ float ks_s[MAXDET];
    __shared__ int   ka_s[MAXDET];
    __shared__ int   scnt;

    for (int pair = blockIdx.x; pair < NPAIR; pair += gridDim.x) {
        __syncthreads();                 // separate iterations
        if (!g_flag[pair]) continue;     // uniform per block

        const int b = pair / NC;
        const int c = pair % NC;
        const float4* __restrict__ bb = (const float4*)(boxes + (size_t)b * NA * 4);
        const float* __restrict__ sc = cls + (size_t)b * NA * NC + c;

        float s[IPT];
#pragma unroll
        for (int i = 0; i < IPT; i++) {
            int a = i * T1 + t;
            float v = (a < NA) ? sc[(size_t)a * NC] : NEGV;
            s[i] = (v > SCORE_THR) ? v : NEGV;
        }

        if (t == 0) scnt = 0;

        bool exhausted = false;

        for (int it = 0; it < MAXDET; it++) {
            float bv = NEGV;
            int   bi = 0x7FFFFFFF;
#pragma unroll
            for (int i = 0; i < IPT; i++) {
                if (s[i] > bv) { bv = s[i]; bi = i * T1 + t; }
            }
#pragma unroll
            for (int o = 16; o; o >>= 1) {
                float ov = __shfl_down_sync(0xffffffffu, bv, o);
                int   oi = __shfl_down_sync(0xffffffffu, bi, o);
                if (ov > bv || (ov == bv && oi < bi)) { bv = ov; bi = oi; }
            }
            if ((t & 31) == 0) { wv[t >> 5] = bv; wi[t >> 5] = bi; }
            __syncthreads();
            if (t < 32) {
                bv = wv[t]; bi = wi[t];
#pragma unroll
                for (int o = 16; o; o >>= 1) {
                    float ov = __shfl_down_sync(0xffffffffu, bv, o);
                    int   oi = __shfl_down_sync(0xffffffffu, bi, o);
                    if (ov > bv || (ov == bv && oi < bi)) { bv = ov; bi = oi; }
                }
                if (t == 0) {
                    if (bv > -0.5e30f) {
                        float4 bx = bb[bi];
                        sbox[0] = bx.x; sbox[1] = bx.y; sbox[2] = bx.z; sbox[3] = bx.w;
                        ssel = bi;
                        int k = scnt;
                        ks_s[k] = bv;
                        ka_s[k] = bi;
                        scnt = k + 1;
                    } else {
                        ssel = -1;
                    }
                }
            }
            __syncthreads();

            int sel = ssel;
            if (sel < 0) { exhausted = true; break; }

            float y1 = sbox[0], x1 = sbox[1], y2 = sbox[2], x2 = sbox[3];
            float sarea = (y2 - y1) * (x2 - x1);
#pragma unroll
            for (int i = 0; i < IPT; i++) {
                if (s[i] > -1e29f) {
                    int a = i * T1 + t;
                    float4 bx = bb[a];
                    float iy1 = fmaxf(y1, bx.x);
                    float ix1 = fmaxf(x1, bx.y);
                    float iy2 = fminf(y2, bx.z);
                    float ix2 = fminf(x2, bx.w);
                    float inter = fmaxf(iy2 - iy1, 0.0f) * fmaxf(ix2 - ix1, 0.0f);
                    float barea = (bx.z - bx.x) * (bx.w - bx.y);
                    float iou = inter / (sarea + barea - inter + 1e-8f);
                    if (iou > IOU_THR) s[i] = NEGV;
                    if (a == sel)      s[i] = NEGV;
                }
            }
            __syncthreads();
        }

        __syncthreads();
        if (t == 0) {
            int cnt = scnt;
            if (exhausted) {
                for (int k = 0; k < cnt; k++) {
                    if (ka_s[k] == 0) {
                        for (int m2 = k; m2 < cnt - 1; m2++) {
                            ks_s[m2] = ks_s[m2 + 1];
                            ka_s[m2] = ka_s[m2 + 1];
                        }
                        cnt--;
                        break;
                    }
                }
                scnt = cnt;
            }
        }
        __syncthreads();
        int cnt = scnt;
        int base2 = pair * MAXDET;
        if (t < cnt) {
            g_ks[base2 + t] = ks_s[t];
            g_ka[base2 + t] = ka_s[t];
        }
        if (t == 0) g_kc[pair] = cnt;
    }
}

// ---------------------------------------------------------------------------
// topk: histogram-select over all kept keys, exact rank selection of the
// top-100 compacted prefix. Serial 90-way merge retained as a guarded
// fallback for pathological distributions.
// ---------------------------------------------------------------------------
#define TT 512
#define CAPC 1024
#define TOPK_DYN (NC * MAXDET * 8)

__device__ __forceinline__ int desc_bin(u64 k)
{
    float s = __uint_as_float((u32)(k >> 32));
    int bin = (int)((s - T0) * BINSCALE);
    bin = min(max(bin, 0), NBIN - 1);
    return NBIN - 1 - bin;
}

__global__ __launch_bounds__(TT) void topk_kernel(const float* __restrict__ boxes,
                                                  float* __restrict__ out)
{
    const int b = blockIdx.x;
    const int t = threadIdx.x;

    extern __shared__ u64 skey[];   // NC*MAXDET

    __shared__ int   cnts[NC];
    __shared__ u32   hist[NBIN];    // histogram -> inclusive cumulative
    __shared__ u64   comp[CAPC];
    __shared__ u64   sel[MAXDET];
    __shared__ u32   warpsum[16];
    __shared__ int   s_cut, s_M, s_nw;

    if (t < NC) cnts[t] = g_kc[b * NC + t];
    for (int i = t; i < NBIN; i += TT) hist[i] = 0;
    if (t == 0) { s_cut = NBIN - 1; s_M = 0; }
    __syncthreads();

    for (int i = t; i < NC * MAXDET; i += TT) {
        int c = i / MAXDET, j = i % MAXDET;
        u64 key = 0ull;
        if (j < cnts[c]) {
            int pb = (b * NC + c) * MAXDET + j;
            float sv = g_ks[pb];
            int   av = g_ka[pb];
            u32 flat = (u32)av * NC + (u32)c;
            key = ((u64)__float_as_uint(sv) << 32) | (0xFFFFFFFFu - flat);
            atomicAdd(&hist[desc_bin(key)], 1u);
        }
        skey[i] = key;
    }
    __syncthreads();

    // inclusive prefix over NBIN bins (4 bins/thread, 16 warps)
    {
        u32 c0 = hist[4 * t], c1 = hist[4 * t + 1];
        u32 c2 = hist[4 * t + 2], c3 = hist[4 * t + 3];
        u32 tsum = c0 + c1 + c2 + c3;
        u32 lane = t & 31, w = t >> 5;
        u32 x = tsum;
#pragma unroll
        for (int o = 1; o < 32; o <<= 1) {
            u32 y = __shfl_up_sync(0xffffffffu, x, o);
            if (lane >= (u32)o) x += y;
        }
        if (lane == 31) warpsum[w] = x;
        __syncthreads();
        if (t == 0) {
            u32 r = 0;
#pragma unroll
            for (int i2 = 0; i2 < 16; i2++) { u32 v = warpsum[i2]; warpsum[i2] = r; r += v; }
        }
        __syncthreads();
        u32 ex = warpsum[w] + x - tsum;   // exclusive prefix of this thread's 4 bins
        hist[4 * t + 0] = ex + c0;
        hist[4 * t + 1] = ex + c0 + c1;
        hist[4 * t + 2] = ex + c0 + c1 + c2;
        hist[4 * t + 3] = ex + tsum;
    }
    __syncthreads();

    // find cutoff: first bin d (desc order) with cumulative >= MAXDET
    for (int q = 0; q < 4; q++) {
        int d = 4 * t + q;
        u32 cum = hist[d];
        u32 prev = (d == 0) ? 0u : hist[d - 1];
        if (cum >= (u32)MAXDET && prev < (u32)MAXDET) s_cut = d;  // unique writer
    }
    __syncthreads();
    int cut = s_cut;

    // compact keys in bins <= cut
    for (int i = t; i < NC * MAXDET; i += TT) {
        u64 k = skey[i];
        if (k && desc_bin(k) <= cut) {
            int p = atomicAdd(&s_M, 1);
            if (p < CAPC) comp[p] = k;
        }
    }
    __syncthreads();
    int M = s_M;

    if (M <= CAPC) {
        // exact rank selection: rank = #{keys greater}; keys are unique
        for (int x = t; x < M; x += TT) {
            u64 mk = comp[x];
            int rank = 0;
            for (int j = 0; j < M; j++) rank += (comp[j] > mk);
            if (rank < MAXDET) sel[rank] = mk;
        }
        if (t == 0) s_nw = (M < MAXDET) ? M : MAXDET;
    } else if (t < 32) {
        // fallback: serial 90-way merge of sorted per-class lists
        const int lane = t;
        u64 hk[3];
        int hj[3];
#pragma unroll
        for (int q = 0; q < 3; q++) {
            int c = lane + q * 32;
            hj[q] = 0;
            hk[q] = (c < NC) ? skey[c * MAXDET] : 0ull;
        }
        int nw = MAXDET;
        for (int k = 0; k < MAXDET; k++) {
            u64 bvk = hk[0];
            int bq = 0;
            if (hk[1] > bvk) { bvk = hk[1]; bq = 1; }
            if (hk[2] > bvk) { bvk = hk[2]; bq = 2; }
            u64 rv = bvk;
            int rl = lane, rq = bq;
#pragma unroll
            for (int o = 16; o; o >>= 1) {
                u64 ov = __shfl_down_sync(0xffffffffu, rv, o);
                int ol = __shfl_down_sync(0xffffffffu, rl, o);
                int oq = __shfl_down_sync(0xffffffffu, rq, o);
                if (ov > rv) { rv = ov; rl = ol; rq = oq; }
            }
            rv = __shfl_sync(0xffffffffu, rv, 0);
            rl = __shfl_sync(0xffffffffu, rl, 0);
            rq = __shfl_sync(0xffffffffu, rq, 0);
            if (rv == 0ull) { nw = k; break; }
            if (lane == 0) sel[k] = rv;
            if (lane == rl) {
                hj[rq]++;
                int c = lane + rq * 32;
                hk[rq] = (hj[rq] < MAXDET) ? skey[c * MAXDET + hj[rq]] : 0ull;
            }
        }
        if (lane == 0) s_nw = nw;
    }
    __syncthreads();

    int nw = s_nw;
    const float4* __restrict__ bb = (const float4*)(boxes + (size_t)b * NA * 4);
    float* ob = out + (size_t)b * MAXDET * 4;
    float* os = out + (size_t)NB * MAXDET * 4 + (size_t)b * MAXDET;
    float* ol = out + (size_t)NB * MAXDET * 5 + (size_t)b * MAXDET;

    if (t < MAXDET) {
        if (t < nw) {
            u64 rv = sel[t];
            u32 flat = 0xFFFFFFFFu - (u32)rv;
            int anchor = (int)(flat / NC);
            int lab = (int)(flat % NC);
            float4 bx = bb[anchor];
            ob[t * 4 + 0] = bx.x;
            ob[t * 4 + 1] = bx.y;
            ob[t * 4 + 2] = bx.z;
            ob[t * 4 + 3] = bx.w;
            os[t] = __uint_as_float((u32)(rv >> 32));
            ol[t] = (float)lab;
        } else {
            ob[t * 4 + 0] = -1.0f;
            ob[t * 4 + 1] = -1.0f;
            ob[t * 4 + 2] = -1.0f;
            ob[t * 4 + 3] = -1.0f;
            os[t] = -1.0f;
            ol[t] = -1.0f;
        }
    }
}

// ---------------------------------------------------------------------------
extern "C" void kernel_launch(void* const* d_in, const int* in_sizes, int n_in,
                              void* d_out, int out_size)
{
    const float* boxes = (const float*)d_in[0];
    const float* cls   = (const float*)d_in[1];
    float* out = (float*)d_out;

    cudaFuncSetAttribute(fused_kernel, cudaFuncAttributeMaxDynamicSharedMemorySize, DYN_BYTES);
    cudaFuncSetAttribute(topk_kernel, cudaFuncAttributeMaxDynamicSharedMemorySize, TOPK_DYN);

    init_kernel<<<12, 512>>>();
    gather_kernel<<<2160, TG>>>(cls);
    fused_kernel<<<NPAIR, TF2, DYN_BYTES>>>(boxes);
    fallback_kernel<<<148, T1>>>(boxes, cls);
    topk_kernel<<<NB, TT, TOPK_DYN>>>(boxes, out);
}